// round 4
// baseline (speedup 1.0000x reference)
#include <cuda_runtime.h>
#include <cuda_bf16.h>

#define PMAX 118
#define NMAX 236
#define D 32
#define PAD_N 240
#define FULL 0xffffffffu

__device__ float  g_Ap[PMAX * D];        // W1[:, :32] @ p_state + b1   (row-major, 32/row)
__device__ float  g_AnT[D * PAD_N];      // transposed: AnT[t][j] = (W1[:,32:] @ n_state_j)[t]
__device__ float  g_G[2 * D];            // G[k][t] = (Wr@W2)[k][t] * ln_g[t]
__device__ float  g_consts[4];           // sG0, sG1, d0, d1
__device__ float2 g_table[PMAX * NMAX];

__device__ __forceinline__ float silu_f(float v) {
    return __fdividef(v, 1.0f + __expf(-v));
}

__device__ __forceinline__ unsigned long long pack2(float lo, float hi) {
    unsigned long long r;
    asm("mov.b64 %0, {%1, %2};" : "=l"(r) : "f"(lo), "f"(hi));
    return r;
}
__device__ __forceinline__ void unpack2(unsigned long long v, float& lo, float& hi) {
    asm("mov.b64 {%0, %1}, %2;" : "=f"(lo), "=f"(hi) : "l"(v));
}
__device__ __forceinline__ unsigned long long fma2(unsigned long long a,
                                                   unsigned long long b,
                                                   unsigned long long c) {
    unsigned long long d;
    asm("fma.rn.f32x2 %0, %1, %2, %3;" : "=l"(d) : "l"(a), "l"(b), "l"(c));
    return d;
}
__device__ __forceinline__ unsigned long long add2(unsigned long long a,
                                                   unsigned long long b) {
    unsigned long long d;
    asm("add.rn.f32x2 %0, %1, %2;" : "=l"(d) : "l"(a), "l"(b));
    return d;
}

// ---------------------------------------------------------------------------
// Kernel 1: chains + constants + pipelined projection, one block, 512 threads.
//   warp 0: proton chain (118 steps)       warp 1: neutron chain (236 steps)
//   warp 2: tail constants (G, consts)
//   warps 3-7:  proton projection (consume states as produced)
//   warps 8-15: neutron projection (consume states as produced)
// ---------------------------------------------------------------------------
__global__ void __launch_bounds__(512, 1)
chains_kernel(const float* __restrict__ emb,
              const float* __restrict__ Wp, const float* __restrict__ bp,
              const float* __restrict__ Wn, const float* __restrict__ bn,
              const float* __restrict__ W1, const float* __restrict__ b1,
              const float* __restrict__ ln_g, const float* __restrict__ ln_b,
              const float* __restrict__ W2, const float* __restrict__ b2,
              const float* __restrict__ Wr, const float* __restrict__ br)
{
    __shared__ __align__(16) float s_state[(PMAX + NMAX) * D];  // 45312 B
    __shared__ __align__(16) float sbuf[2][2][D];
    __shared__ int prog[2];   // published step counts: [0]=proton, [1]=neutron

    const int wid  = threadIdx.x >> 5;
    const int lane = threadIdx.x & 31;

    if (threadIdx.x < 2) prog[threadIdx.x] = 0;
    __syncthreads();          // the ONLY block-wide sync; everything after is spin-based

    if (wid <= 1) {
        // ------------------ serial chain ------------------
        const float* W    = (wid == 0) ? Wp : Wn;
        const float* bias = (wid == 0) ? bp : bn;
        const int    len  = (wid == 0) ? PMAX : NMAX;
        const int    base = (wid == 0) ? 0 : PMAX;

        unsigned long long wp[16];
        #pragma unroll
        for (int k = 0; k < 16; k++)
            wp[k] = pack2(W[lane * D + 2 * k], W[lane * D + 2 * k + 1]);
        const unsigned long long bpk  = pack2(bias[lane], 0.0f);
        const unsigned long long zero = pack2(0.0f, 0.0f);

        float p = emb[wid * D + lane];

        for (int s = 0; s < len; s++) {
            const int par = s & 1;
            const float sp = silu_f(p);
            sbuf[wid][par][lane] = sp;
            __syncwarp();

            const ulonglong2* v = (const ulonglong2*)sbuf[wid][par];
            const ulonglong2 q0 = v[0], q1 = v[1], q2 = v[2], q3 = v[3];
            const ulonglong2 q4 = v[4], q5 = v[5], q6 = v[6], q7 = v[7];

            unsigned long long a0 = fma2(wp[0],  q0.x, bpk);
            unsigned long long a1 = fma2(wp[2],  q1.x, zero);
            unsigned long long a2 = fma2(wp[4],  q2.x, zero);
            unsigned long long a3 = fma2(wp[6],  q3.x, zero);
            unsigned long long a4 = fma2(wp[8],  q4.x, zero);
            unsigned long long a5 = fma2(wp[10], q5.x, zero);
            unsigned long long a6 = fma2(wp[12], q6.x, zero);
            unsigned long long a7 = fma2(wp[14], q7.x, zero);

            a0 = fma2(wp[1],  q0.y, a0);
            a1 = fma2(wp[3],  q1.y, a1);
            a2 = fma2(wp[5],  q2.y, a2);
            a3 = fma2(wp[7],  q3.y, a3);
            a4 = fma2(wp[9],  q4.y, a4);
            a5 = fma2(wp[11], q5.y, a5);
            a6 = fma2(wp[13], q6.y, a6);
            a7 = fma2(wp[15], q7.y, a7);

            const unsigned long long c0 = add2(add2(a0, a1), add2(a2, a3));
            const unsigned long long c1 = add2(add2(a4, a5), add2(a6, a7));
            const unsigned long long dd = add2(c0, c1);
            float lo, hi;
            unpack2(dd, lo, hi);
            p = lo + hi;

            s_state[(base + s) * D + lane] = p;

            if ((s & 7) == 7) {
                __threadfence_block();
                if (lane == 0) prog[wid] = s + 1;
            }
        }
        __threadfence_block();
        if (lane == 0) prog[wid] = len;
    }
    else if (wid == 2) {
        // ------------------ fused tail constants ------------------
        const int t = lane;
        float m0 = 0.f, m1 = 0.f;
        #pragma unroll
        for (int u = 0; u < D; u++) {
            const float w2 = W2[u * D + t];
            m0 = fmaf(Wr[u],     w2, m0);
            m1 = fmaf(Wr[D + u], w2, m1);
        }
        const float g  = ln_g[t];
        const float lb = ln_b[t];
        g_G[t]     = m0 * g;
        g_G[D + t] = m1 * g;

        float sG0 = m0 * g;
        float sG1 = m1 * g;
        float d0  = fmaf(m0, lb, Wr[t]     * b2[t]);
        float d1  = fmaf(m1, lb, Wr[D + t] * b2[t]);
        #pragma unroll
        for (int off = 16; off > 0; off >>= 1) {
            sG0 += __shfl_xor_sync(FULL, sG0, off);
            sG1 += __shfl_xor_sync(FULL, sG1, off);
            d0  += __shfl_xor_sync(FULL, d0,  off);
            d1  += __shfl_xor_sync(FULL, d1,  off);
        }
        if (lane == 0) {
            g_consts[0] = sG0;
            g_consts[1] = sG1;
            g_consts[2] = d0 + br[0];
            g_consts[3] = d1 + br[1];
        }
    }
    else {
        // ------------------ pipelined projection ------------------
        const bool proton = (wid < 8);
        const int  widx   = proton ? (wid - 3) : (wid - 8);
        const int  stride = proton ? 5 : 8;
        const int  len    = proton ? PMAX : NMAX;
        const int  base   = proton ? 0 : PMAX;
        const int  coff   = proton ? 0 : D;     // column offset into W1
        const int  pidx   = proton ? 0 : 1;

        float w[D];
        #pragma unroll
        for (int j = 0; j < D; j++) w[j] = W1[lane * (2 * D) + coff + j];
        const float bias = proton ? b1[lane] : 0.0f;

        volatile int* vp = &prog[pidx];

        for (int r = widx; r < len; r += stride) {
            while (*vp <= r) __nanosleep(64);
            __threadfence_block();

            const float4* s4 = (const float4*)&s_state[(base + r) * D];
            float acc = bias;
            #pragma unroll
            for (int q = 0; q < 8; q++) {
                const float4 xv = s4[q];
                acc = fmaf(w[4 * q + 0], xv.x, acc);
                acc = fmaf(w[4 * q + 1], xv.y, acc);
                acc = fmaf(w[4 * q + 2], xv.z, acc);
                acc = fmaf(w[4 * q + 3], xv.w, acc);
            }

            if (proton) g_Ap[r * D + lane] = acc;
            else        g_AnT[lane * PAD_N + r] = acc;
        }
    }
}

// ---------------------------------------------------------------------------
// Kernel 2: build pair table, ONE THREAD per (i, j) pair. No shuffles.
// out_k = rs * (dot(G_k, s) - mu * sumG_k) + d_k
// ---------------------------------------------------------------------------
__global__ void table_kernel()
{
    __shared__ float sG[2 * D];
    __shared__ float sC[4];

    if (threadIdx.x < 2 * D) sG[threadIdx.x] = g_G[threadIdx.x];
    if (threadIdx.x < 4)     sC[threadIdx.x] = g_consts[threadIdx.x];
    __syncthreads();

    const int pair = blockIdx.x * blockDim.x + threadIdx.x;
    if (pair >= PMAX * NMAX) return;

    const int i = pair / NMAX;
    const int j = pair - i * NMAX;

    const float4* ap4 = (const float4*)&g_Ap[i * D];

    float r0 = 0.f, r1 = 0.f, r2 = 0.f, r3 = 0.f;
    #pragma unroll
    for (int q = 0; q < 8; q++) {
        const float4 a = ap4[q];
        const int t = 4 * q;
        {
            const float s = silu_f(a.x + g_AnT[(t + 0) * PAD_N + j]);
            r0 += s; r1 = fmaf(s, s, r1);
            r2 = fmaf(sG[t + 0], s, r2); r3 = fmaf(sG[D + t + 0], s, r3);
        }
        {
            const float s = silu_f(a.y + g_AnT[(t + 1) * PAD_N + j]);
            r0 += s; r1 = fmaf(s, s, r1);
            r2 = fmaf(sG[t + 1], s, r2); r3 = fmaf(sG[D + t + 1], s, r3);
        }
        {
            const float s = silu_f(a.z + g_AnT[(t + 2) * PAD_N + j]);
            r0 += s; r1 = fmaf(s, s, r1);
            r2 = fmaf(sG[t + 2], s, r2); r3 = fmaf(sG[D + t + 2], s, r3);
        }
        {
            const float s = silu_f(a.w + g_AnT[(t + 3) * PAD_N + j]);
            r0 += s; r1 = fmaf(s, s, r1);
            r2 = fmaf(sG[t + 3], s, r2); r3 = fmaf(sG[D + t + 3], s, r3);
        }
    }

    const float mu  = r0 * (1.0f / D);
    const float var = r1 * (1.0f / D) - mu * mu;
    const float rs  = rsqrtf(var + 1e-5f);
    const float o0  = rs * (r2 - mu * sC[0]) + sC[2];
    const float o1  = rs * (r3 - mu * sC[1]) + sC[3];
    g_table[pair] = make_float2(o0, o1);
}

// ---------------------------------------------------------------------------
// Kernel 3: gather. 4 int4 (= 8 batch elements) per thread; 8 lookups in flight.
// ---------------------------------------------------------------------------
__global__ void gather_kernel(const int4* __restrict__ x4,
                              float4* __restrict__ out4, int H)
{
    const int t = blockIdx.x * blockDim.x + threadIdx.x;
    if (t >= H) return;

    const int4 v0 = x4[t];
    const int4 v1 = x4[t + H];
    const int4 v2 = x4[t + 2 * H];
    const int4 v3 = x4[t + 3 * H];

    const float2 a0 = g_table[(v0.x - 1) * NMAX + (v0.y - 1)];
    const float2 b0 = g_table[(v0.z - 1) * NMAX + (v0.w - 1)];
    const float2 a1 = g_table[(v1.x - 1) * NMAX + (v1.y - 1)];
    const float2 b1 = g_table[(v1.z - 1) * NMAX + (v1.w - 1)];
    const float2 a2 = g_table[(v2.x - 1) * NMAX + (v2.y - 1)];
    const float2 b2 = g_table[(v2.z - 1) * NMAX + (v2.w - 1)];
    const float2 a3 = g_table[(v3.x - 1) * NMAX + (v3.y - 1)];
    const float2 b3 = g_table[(v3.z - 1) * NMAX + (v3.w - 1)];

    out4[t]         = make_float4(a0.x, a0.y, b0.x, b0.y);
    out4[t + H]     = make_float4(a1.x, a1.y, b1.x, b1.y);
    out4[t + 2 * H] = make_float4(a2.x, a2.y, b2.x, b2.y);
    out4[t + 3 * H] = make_float4(a3.x, a3.y, b3.x, b3.y);
}

__global__ void gather_tail_kernel(const int2* __restrict__ x2,
                                   float2* __restrict__ out2, int start, int n)
{
    const int t = start + blockIdx.x * blockDim.x + threadIdx.x;
    if (t >= n) return;
    const int2 v = x2[t];
    out2[t] = g_table[(v.x - 1) * NMAX + (v.y - 1)];
}

// ---------------------------------------------------------------------------
extern "C" void kernel_launch(void* const* d_in, const int* in_sizes, int n_in,
                              void* d_out, int out_size)
{
    const int*   x    = (const int*)  d_in[0];
    const float* emb  = (const float*)d_in[1];
    const float* Wp   = (const float*)d_in[2];
    const float* bp   = (const float*)d_in[3];
    const float* Wn   = (const float*)d_in[4];
    const float* bn   = (const float*)d_in[5];
    const float* W1   = (const float*)d_in[6];
    const float* b1   = (const float*)d_in[7];
    const float* ln_g = (const float*)d_in[8];
    const float* ln_b = (const float*)d_in[9];
    const float* W2   = (const float*)d_in[10];
    const float* b2   = (const float*)d_in[11];
    const float* Wr   = (const float*)d_in[12];
    const float* br   = (const float*)d_in[13];

    const int B = in_sizes[0] / 2;   // x is [B, 2]

    chains_kernel<<<1, 512>>>(emb, Wp, bp, Wn, bn, W1, b1,
                              ln_g, ln_b, W2, b2, Wr, br);

    {
        const int pairs  = PMAX * NMAX;          // 27848
        const int blocks = (pairs + 255) / 256;
        table_kernel<<<blocks, 256>>>();
    }

    {
        const int n4 = B / 2;                    // int4 count
        const int H  = n4 / 4;                   // 4 int4 per thread
        if (H > 0) {
            const int blocks = (H + 255) / 256;
            gather_kernel<<<blocks, 256>>>((const int4*)x, (float4*)d_out, H);
        }
        const int done = 8 * (n4 / 4);           // batch elements covered
        if (done < B) {
            const int rem = B - done;
            gather_tail_kernel<<<(rem + 255) / 256, 256>>>(
                (const int2*)x, (float2*)d_out, done, B);
        }
    }
}

// round 5
// speedup vs baseline: 1.4591x; 1.4591x over previous
#include <cuda_runtime.h>
#include <cuda_bf16.h>

#define PMAX 118
#define NMAX 236
#define D 32
#define PAD_N 240
#define FULL 0xffffffffu

__device__ float  g_Ap[PMAX * D];        // W1[:, :32] @ p_state + b1
__device__ float  g_AnT[D * PAD_N];      // AnT[t][j] = (W1[:,32:] @ n_state_j)[t]
__device__ float  g_G[2 * D];            // G[k][t] = (Wr@W2)[k][t] * ln_g[t]
__device__ float  g_consts[4];           // sG0, sG1, d0, d1
__device__ float2 g_table[PMAX * NMAX];

__device__ __forceinline__ float silu_f(float v) {
    return __fdividef(v, 1.0f + __expf(-v));
}

__device__ __forceinline__ unsigned long long pack2(float lo, float hi) {
    unsigned long long r;
    asm("mov.b64 %0, {%1, %2};" : "=l"(r) : "f"(lo), "f"(hi));
    return r;
}
__device__ __forceinline__ void unpack2(unsigned long long v, float& lo, float& hi) {
    asm("mov.b64 {%0, %1}, %2;" : "=f"(lo), "=f"(hi) : "l"(v));
}
__device__ __forceinline__ unsigned long long fma2(unsigned long long a,
                                                   unsigned long long b,
                                                   unsigned long long c) {
    unsigned long long d;
    asm("fma.rn.f32x2 %0, %1, %2, %3;" : "=l"(d) : "l"(a), "l"(b), "l"(c));
    return d;
}
__device__ __forceinline__ unsigned long long add2(unsigned long long a,
                                                   unsigned long long b) {
    unsigned long long d;
    asm("add.rn.f32x2 %0, %1, %2;" : "=l"(d) : "l"(a), "l"(b));
    return d;
}

// ---------------------------------------------------------------------------
// Kernel 1: chains + constants + projection. One block, 512 threads.
//   warp 15: neutron chain (236 steps)   warp 14: proton chain (118 steps)
//     -> highest wids = highest arbiter priority (hi-wid-first)
//   warp 0:  tail constants, pre-barrier
//   warps 0-13: park at __syncthreads (no issue pressure), then project
//     warps 0-4  (stride 5): proton rows -> g_Ap
//     warps 5-13 (stride 9): neutron rows -> g_AnT (transposed)
// ---------------------------------------------------------------------------
__global__ void __launch_bounds__(512, 1)
chains_kernel(const float* __restrict__ emb,
              const float* __restrict__ Wp, const float* __restrict__ bp,
              const float* __restrict__ Wn, const float* __restrict__ bn,
              const float* __restrict__ W1, const float* __restrict__ b1,
              const float* __restrict__ ln_g, const float* __restrict__ ln_b,
              const float* __restrict__ W2, const float* __restrict__ b2,
              const float* __restrict__ Wr, const float* __restrict__ br)
{
    __shared__ __align__(16) float s_state[(PMAX + NMAX) * D];  // 45312 B
    __shared__ __align__(16) float sbuf[2][2][D];

    const int wid  = threadIdx.x >> 5;
    const int lane = threadIdx.x & 31;

    // projector weight registers (loaded pre-barrier by projector warps)
    float pw[D];
    float pbias = 0.0f;

    if (wid >= 14) {
        // ------------------ serial chain ------------------
        const int    c    = wid - 14;            // 0 = proton, 1 = neutron
        const float* W    = (c == 0) ? Wp : Wn;
        const float* bias = (c == 0) ? bp : bn;
        const int    len  = (c == 0) ? PMAX : NMAX;
        const int    base = (c == 0) ? 0 : PMAX;

        unsigned long long wp[16];
        #pragma unroll
        for (int k = 0; k < 16; k++)
            wp[k] = pack2(W[lane * D + 2 * k], W[lane * D + 2 * k + 1]);
        const unsigned long long bpk  = pack2(bias[lane], 0.0f);
        const unsigned long long zero = pack2(0.0f, 0.0f);

        float p = emb[c * D + lane];

        for (int s = 0; s < len; s++) {
            const int par = s & 1;
            const float sp = silu_f(p);
            sbuf[c][par][lane] = sp;
            __syncwarp();

            const ulonglong2* v = (const ulonglong2*)sbuf[c][par];
            const ulonglong2 q0 = v[0], q1 = v[1], q2 = v[2], q3 = v[3];
            const ulonglong2 q4 = v[4], q5 = v[5], q6 = v[6], q7 = v[7];

            unsigned long long a0 = fma2(wp[0],  q0.x, bpk);
            unsigned long long a1 = fma2(wp[2],  q1.x, zero);
            unsigned long long a2 = fma2(wp[4],  q2.x, zero);
            unsigned long long a3 = fma2(wp[6],  q3.x, zero);
            unsigned long long a4 = fma2(wp[8],  q4.x, zero);
            unsigned long long a5 = fma2(wp[10], q5.x, zero);
            unsigned long long a6 = fma2(wp[12], q6.x, zero);
            unsigned long long a7 = fma2(wp[14], q7.x, zero);

            a0 = fma2(wp[1],  q0.y, a0);
            a1 = fma2(wp[3],  q1.y, a1);
            a2 = fma2(wp[5],  q2.y, a2);
            a3 = fma2(wp[7],  q3.y, a3);
            a4 = fma2(wp[9],  q4.y, a4);
            a5 = fma2(wp[11], q5.y, a5);
            a6 = fma2(wp[13], q6.y, a6);
            a7 = fma2(wp[15], q7.y, a7);

            const unsigned long long c0 = add2(add2(a0, a1), add2(a2, a3));
            const unsigned long long c1 = add2(add2(a4, a5), add2(a6, a7));
            float lo, hi;
            unpack2(add2(c0, c1), lo, hi);
            p = lo + hi;

            s_state[(base + s) * D + lane] = p;
        }
    }
    else {
        if (wid == 0) {
            // ------------------ fused tail constants ------------------
            const int t = lane;
            float m0 = 0.f, m1 = 0.f;
            #pragma unroll
            for (int u = 0; u < D; u++) {
                const float w2 = W2[u * D + t];
                m0 = fmaf(Wr[u],     w2, m0);
                m1 = fmaf(Wr[D + u], w2, m1);
            }
            const float g  = ln_g[t];
            const float lb = ln_b[t];
            g_G[t]     = m0 * g;
            g_G[D + t] = m1 * g;

            float sG0 = m0 * g;
            float sG1 = m1 * g;
            float d0  = fmaf(m0, lb, Wr[t]     * b2[t]);
            float d1  = fmaf(m1, lb, Wr[D + t] * b2[t]);
            #pragma unroll
            for (int off = 16; off > 0; off >>= 1) {
                sG0 += __shfl_xor_sync(FULL, sG0, off);
                sG1 += __shfl_xor_sync(FULL, sG1, off);
                d0  += __shfl_xor_sync(FULL, d0,  off);
                d1  += __shfl_xor_sync(FULL, d1,  off);
            }
            if (lane == 0) {
                g_consts[0] = sG0;
                g_consts[1] = sG1;
                g_consts[2] = d0 + br[0];
                g_consts[3] = d1 + br[1];
            }
        }
        // projector weights: warps 0-4 proton columns, 5-13 neutron columns
        const int coff = (wid < 5) ? 0 : D;
        #pragma unroll
        for (int j = 0; j < D; j++) pw[j] = W1[lane * (2 * D) + coff + j];
        if (wid < 5) pbias = b1[lane];
    }

    __syncthreads();   // chains done; states visible to all

    if (wid < 14) {
        // ------------------ projection ------------------
        const bool proton = (wid < 5);
        const int  widx   = proton ? wid : (wid - 5);
        const int  stride = proton ? 5 : 9;
        const int  len    = proton ? PMAX : NMAX;
        const int  base   = proton ? 0 : PMAX;

        for (int r = widx; r < len; r += stride) {
            const float4* s4 = (const float4*)&s_state[(base + r) * D];
            float acc = pbias;
            #pragma unroll
            for (int q = 0; q < 8; q++) {
                const float4 xv = s4[q];
                acc = fmaf(pw[4 * q + 0], xv.x, acc);
                acc = fmaf(pw[4 * q + 1], xv.y, acc);
                acc = fmaf(pw[4 * q + 2], xv.z, acc);
                acc = fmaf(pw[4 * q + 3], xv.w, acc);
            }
            if (proton) g_Ap[r * D + lane] = acc;
            else        g_AnT[lane * PAD_N + r] = acc;
        }
    }
}

// ---------------------------------------------------------------------------
// Kernel 2: build pair table, one thread per (i, j) pair. No shuffles.
// ---------------------------------------------------------------------------
__global__ void table_kernel()
{
    __shared__ float sG[2 * D];
    __shared__ float sC[4];

    if (threadIdx.x < 2 * D) sG[threadIdx.x] = g_G[threadIdx.x];
    if (threadIdx.x < 4)     sC[threadIdx.x] = g_consts[threadIdx.x];
    __syncthreads();

    const int pair = blockIdx.x * blockDim.x + threadIdx.x;
    if (pair >= PMAX * NMAX) return;

    const int i = pair / NMAX;
    const int j = pair - i * NMAX;

    const float4* ap4 = (const float4*)&g_Ap[i * D];

    float r0 = 0.f, r1 = 0.f, r2 = 0.f, r3 = 0.f;
    #pragma unroll
    for (int q = 0; q < 8; q++) {
        const float4 a = ap4[q];
        const int t = 4 * q;
        {
            const float s = silu_f(a.x + g_AnT[(t + 0) * PAD_N + j]);
            r0 += s; r1 = fmaf(s, s, r1);
            r2 = fmaf(sG[t + 0], s, r2); r3 = fmaf(sG[D + t + 0], s, r3);
        }
        {
            const float s = silu_f(a.y + g_AnT[(t + 1) * PAD_N + j]);
            r0 += s; r1 = fmaf(s, s, r1);
            r2 = fmaf(sG[t + 1], s, r2); r3 = fmaf(sG[D + t + 1], s, r3);
        }
        {
            const float s = silu_f(a.z + g_AnT[(t + 2) * PAD_N + j]);
            r0 += s; r1 = fmaf(s, s, r1);
            r2 = fmaf(sG[t + 2], s, r2); r3 = fmaf(sG[D + t + 2], s, r3);
        }
        {
            const float s = silu_f(a.w + g_AnT[(t + 3) * PAD_N + j]);
            r0 += s; r1 = fmaf(s, s, r1);
            r2 = fmaf(sG[t + 3], s, r2); r3 = fmaf(sG[D + t + 3], s, r3);
        }
    }

    const float mu  = r0 * (1.0f / D);
    const float var = r1 * (1.0f / D) - mu * mu;
    const float rs  = rsqrtf(var + 1e-5f);
    const float o0  = rs * (r2 - mu * sC[0]) + sC[2];
    const float o1  = rs * (r3 - mu * sC[1]) + sC[3];
    g_table[pair] = make_float2(o0, o1);
}

// ---------------------------------------------------------------------------
// Kernel 3: gather. One int4 (2 batch elements) per thread; max thread count.
// ---------------------------------------------------------------------------
__global__ void gather_kernel(const int4* __restrict__ x4,
                              float4* __restrict__ out4, int n4)
{
    const int t = blockIdx.x * blockDim.x + threadIdx.x;
    if (t >= n4) return;
    const int4 v = x4[t];
    const float2 a = g_table[(v.x - 1) * NMAX + (v.y - 1)];
    const float2 b = g_table[(v.z - 1) * NMAX + (v.w - 1)];
    out4[t] = make_float4(a.x, a.y, b.x, b.y);
}

__global__ void gather_tail_kernel(const int2* __restrict__ x2,
                                   float2* __restrict__ out2, int start, int n)
{
    const int t = start + blockIdx.x * blockDim.x + threadIdx.x;
    if (t >= n) return;
    const int2 v = x2[t];
    out2[t] = g_table[(v.x - 1) * NMAX + (v.y - 1)];
}

// ---------------------------------------------------------------------------
extern "C" void kernel_launch(void* const* d_in, const int* in_sizes, int n_in,
                              void* d_out, int out_size)
{
    const int*   x    = (const int*)  d_in[0];
    const float* emb  = (const float*)d_in[1];
    const float* Wp   = (const float*)d_in[2];
    const float* bp   = (const float*)d_in[3];
    const float* Wn   = (const float*)d_in[4];
    const float* bn   = (const float*)d_in[5];
    const float* W1   = (const float*)d_in[6];
    const float* b1   = (const float*)d_in[7];
    const float* ln_g = (const float*)d_in[8];
    const float* ln_b = (const float*)d_in[9];
    const float* W2   = (const float*)d_in[10];
    const float* b2   = (const float*)d_in[11];
    const float* Wr   = (const float*)d_in[12];
    const float* br   = (const float*)d_in[13];

    const int B = in_sizes[0] / 2;   // x is [B, 2]

    chains_kernel<<<1, 512>>>(emb, Wp, bp, Wn, bn, W1, b1,
                              ln_g, ln_b, W2, b2, Wr, br);

    {
        const int pairs  = PMAX * NMAX;          // 27848
        const int blocks = (pairs + 255) / 256;
        table_kernel<<<blocks, 256>>>();
    }

    {
        const int n4 = B / 2;                    // int4 count (2 elems each)
        if (n4 > 0) {
            const int blocks = (n4 + 255) / 256;
            gather_kernel<<<blocks, 256>>>((const int4*)x, (float4*)d_out, n4);
        }
        const int done = 2 * n4;
        if (done < B) {
            const int rem = B - done;
            gather_tail_kernel<<<(rem + 255) / 256, 256>>>(
                (const int2*)x, (float2*)d_out, done, B);
        }
    }
}

// round 7
// speedup vs baseline: 1.5322x; 1.0501x over previous
#include <cuda_runtime.h>
#include <cuda_bf16.h>

#define PMAX 118
#define NMAX 236
#define D 32
#define PAD_N 240
#define FULL 0xffffffffu

__device__ float  g_Ap[PMAX * D];        // W1[:, :32] @ p_state + b1
__device__ float  g_AnT[D * PAD_N];      // AnT[t][j] = (W1[:,32:] @ n_state_j)[t]
__device__ float  g_G[2 * D];            // G[k][t] = (Wr@W2)[k][t] * ln_g[t]
__device__ float  g_consts[4];           // sG0, sG1, d0, d1
__device__ float2 g_table[PMAX * NMAX];

__device__ __forceinline__ float silu_f(float v) {
    return __fdividef(v, 1.0f + __expf(-v));
}

__device__ __forceinline__ float ex2f(float x) {
    float r; asm("ex2.approx.ftz.f32 %0, %1;" : "=f"(r) : "f"(x)); return r;
}
__device__ __forceinline__ float rcpf(float x) {
    float r; asm("rcp.approx.ftz.f32 %0, %1;" : "=f"(r) : "f"(x)); return r;
}

__device__ __forceinline__ unsigned long long pack2(float lo, float hi) {
    unsigned long long r;
    asm("mov.b64 %0, {%1, %2};" : "=l"(r) : "f"(lo), "f"(hi));
    return r;
}
__device__ __forceinline__ void unpack2(unsigned long long v, float& lo, float& hi) {
    asm("mov.b64 {%0, %1}, %2;" : "=f"(lo), "=f"(hi) : "l"(v));
}
__device__ __forceinline__ unsigned long long fma2(unsigned long long a,
                                                   unsigned long long b,
                                                   unsigned long long c) {
    unsigned long long d;
    asm("fma.rn.f32x2 %0, %1, %2, %3;" : "=l"(d) : "l"(a), "l"(b), "l"(c));
    return d;
}
__device__ __forceinline__ unsigned long long add2(unsigned long long a,
                                                   unsigned long long b) {
    unsigned long long d;
    asm("add.rn.f32x2 %0, %1, %2;" : "=l"(d) : "l"(a), "l"(b));
    return d;
}

// volatile smem broadcast ops (ordering enforced; warp is convergent so no sync)
__device__ __forceinline__ void sts_vol(unsigned addr, float v) {
    asm volatile("st.volatile.shared.f32 [%0], %1;" :: "r"(addr), "f"(v) : "memory");
}
__device__ __forceinline__ void lds_vol_2u64(unsigned addr,
                                             unsigned long long& a,
                                             unsigned long long& b) {
    asm volatile("ld.volatile.shared.v2.u64 {%0, %1}, [%2];"
                 : "=l"(a), "=l"(b) : "r"(addr) : "memory");
}

// ---------------------------------------------------------------------------
// Kernel 1: chains + constants + projection. One block, 512 threads.
//   warp 15: neutron chain (236 steps)   warp 14: proton chain (118 steps)
//   warp 0:  tail constants, pre-barrier
//   all other warps park at __syncthreads, then project (warps 0-13)
// Chain loop carries y' = -log2e * preactivation; weights pre-scaled so the
// ex2 input is the dot output directly. State p = -ln2 * y' (off-path).
// ---------------------------------------------------------------------------
__global__ void __launch_bounds__(512, 1)
chains_kernel(const float* __restrict__ emb,
              const float* __restrict__ Wp, const float* __restrict__ bp,
              const float* __restrict__ Wn, const float* __restrict__ bn,
              const float* __restrict__ W1, const float* __restrict__ b1,
              const float* __restrict__ ln_g, const float* __restrict__ ln_b,
              const float* __restrict__ W2, const float* __restrict__ b2,
              const float* __restrict__ Wr, const float* __restrict__ br)
{
    __shared__ __align__(16) float s_state[(PMAX + NMAX) * D];  // 45312 B
    __shared__ __align__(16) float sbuf[2][2][D];

    const int wid  = threadIdx.x >> 5;
    const int lane = threadIdx.x & 31;

    float pw[D];
    float pbias = 0.0f;

    if (wid >= 14) {
        // ------------------ serial chain ------------------
        const int    c    = wid - 14;            // 0 = proton, 1 = neutron
        const float* W    = (c == 0) ? Wp : Wn;
        const float* bias = (c == 0) ? bp : bn;
        const int    len  = (c == 0) ? PMAX : NMAX;
        const int    base = (c == 0) ? 0 : PMAX;

        const float S  = -1.4426950408889634f;   // -log2(e)
        const float C2 = -0.6931471805599453f;   // -ln(2)

        unsigned long long wq[16];
        #pragma unroll
        for (int k = 0; k < 16; k++)
            wq[k] = pack2(S * W[lane * D + 2 * k], S * W[lane * D + 2 * k + 1]);
        const unsigned long long bq   = pack2(S * bias[lane], 0.0f);
        const unsigned long long zero = pack2(0.0f, 0.0f);

        const unsigned sb0 = (unsigned)__cvta_generic_to_shared(&sbuf[c][0][0]);
        const unsigned sb1 = (unsigned)__cvta_generic_to_shared(&sbuf[c][1][0]);

        float p  = emb[c * D + lane];
        float yp = S * p;                        // scaled preactivation carry

        for (int s = 0; s < len; s++) {
            const unsigned sb = (s & 1) ? sb1 : sb0;

            // silu(p) = p * rcp(1 + 2^(yp))      [2^(yp) == e^{-p}]
            const float e  = ex2f(yp);
            const float r  = rcpf(1.0f + e);
            const float sp = p * r;

            sts_vol(sb + lane * 4, sp);

            unsigned long long q0a, q0b, q1a, q1b, q2a, q2b, q3a, q3b;
            lds_vol_2u64(sb +  0, q0a, q0b);
            lds_vol_2u64(sb + 16, q1a, q1b);
            lds_vol_2u64(sb + 32, q2a, q2b);
            lds_vol_2u64(sb + 48, q3a, q3b);
            unsigned long long q4a, q4b, q5a, q5b, q6a, q6b, q7a, q7b;
            lds_vol_2u64(sb + 64, q4a, q4b);
            lds_vol_2u64(sb + 80, q5a, q5b);
            lds_vol_2u64(sb + 96, q6a, q6b);
            lds_vol_2u64(sb + 112, q7a, q7b);

            unsigned long long a0 = fma2(wq[0],  q0a, bq);
            unsigned long long a1 = fma2(wq[2],  q1a, zero);
            unsigned long long a2 = fma2(wq[4],  q2a, zero);
            unsigned long long a3 = fma2(wq[6],  q3a, zero);
            unsigned long long a4 = fma2(wq[8],  q4a, zero);
            unsigned long long a5 = fma2(wq[10], q5a, zero);
            unsigned long long a6 = fma2(wq[12], q6a, zero);
            unsigned long long a7 = fma2(wq[14], q7a, zero);

            a0 = fma2(wq[1],  q0b, a0);
            a1 = fma2(wq[3],  q1b, a1);
            a2 = fma2(wq[5],  q2b, a2);
            a3 = fma2(wq[7],  q3b, a3);
            a4 = fma2(wq[9],  q4b, a4);
            a5 = fma2(wq[11], q5b, a5);
            a6 = fma2(wq[13], q6b, a6);
            a7 = fma2(wq[15], q7b, a7);

            const unsigned long long c0 = add2(add2(a0, a1), add2(a2, a3));
            const unsigned long long c1 = add2(add2(a4, a5), add2(a6, a7));
            float lo, hi;
            unpack2(add2(c0, c1), lo, hi);
            yp = lo + hi;                         // new scaled preactivation

            p = C2 * yp;                          // actual state (off-path)
            s_state[(base + s) * D + lane] = p;
        }
    }
    else {
        if (wid == 0) {
            // ------------------ fused tail constants ------------------
            const int t = lane;
            float m0 = 0.f, m1 = 0.f;
            #pragma unroll
            for (int u = 0; u < D; u++) {
                const float w2 = W2[u * D + t];
                m0 = fmaf(Wr[u],     w2, m0);
                m1 = fmaf(Wr[D + u], w2, m1);
            }
            const float g  = ln_g[t];
            const float lb = ln_b[t];
            g_G[t]     = m0 * g;
            g_G[D + t] = m1 * g;

            float sG0 = m0 * g;
            float sG1 = m1 * g;
            float d0  = fmaf(m0, lb, Wr[t]     * b2[t]);
            float d1  = fmaf(m1, lb, Wr[D + t] * b2[t]);
            #pragma unroll
            for (int off = 16; off > 0; off >>= 1) {
                sG0 += __shfl_xor_sync(FULL, sG0, off);
                sG1 += __shfl_xor_sync(FULL, sG1, off);
                d0  += __shfl_xor_sync(FULL, d0,  off);
                d1  += __shfl_xor_sync(FULL, d1,  off);
            }
            if (lane == 0) {
                g_consts[0] = sG0;
                g_consts[1] = sG1;
                g_consts[2] = d0 + br[0];
                g_consts[3] = d1 + br[1];
            }
        }
        // projector weights: warps 0-4 proton columns, 5-13 neutron columns
        const int coff = (wid < 5) ? 0 : D;
        #pragma unroll
        for (int j = 0; j < D; j++) pw[j] = W1[lane * (2 * D) + coff + j];
        if (wid < 5) pbias = b1[lane];
    }

    __syncthreads();   // chains done; states visible to all

    if (wid < 14) {
        // ------------------ projection ------------------
        const bool proton = (wid < 5);
        const int  widx   = proton ? wid : (wid - 5);
        const int  stride = proton ? 5 : 9;
        const int  len    = proton ? PMAX : NMAX;
        const int  base   = proton ? 0 : PMAX;

        for (int r = widx; r < len; r += stride) {
            const float4* s4 = (const float4*)&s_state[(base + r) * D];
            float acc = pbias;
            #pragma unroll
            for (int q = 0; q < 8; q++) {
                const float4 xv = s4[q];
                acc = fmaf(pw[4 * q + 0], xv.x, acc);
                acc = fmaf(pw[4 * q + 1], xv.y, acc);
                acc = fmaf(pw[4 * q + 2], xv.z, acc);
                acc = fmaf(pw[4 * q + 3], xv.w, acc);
            }
            if (proton) g_Ap[r * D + lane] = acc;
            else        g_AnT[lane * PAD_N + r] = acc;
        }
    }
}

// ---------------------------------------------------------------------------
// Kernel 2: build pair table, one thread per (i, j) pair. No shuffles.
// ---------------------------------------------------------------------------
__global__ void table_kernel()
{
    __shared__ float sG[2 * D];
    __shared__ float sC[4];

    if (threadIdx.x < 2 * D) sG[threadIdx.x] = g_G[threadIdx.x];
    if (threadIdx.x < 4)     sC[threadIdx.x] = g_consts[threadIdx.x];
    __syncthreads();

    const int pair = blockIdx.x * blockDim.x + threadIdx.x;
    if (pair >= PMAX * NMAX) return;

    const int i = pair / NMAX;
    const int j = pair - i * NMAX;

    const float4* ap4 = (const float4*)&g_Ap[i * D];

    float r0 = 0.f, r1 = 0.f, r2 = 0.f, r3 = 0.f;
    #pragma unroll
    for (int q = 0; q < 8; q++) {
        const float4 a = ap4[q];
        const int t = 4 * q;
        {
            const float s = silu_f(a.x + g_AnT[(t + 0) * PAD_N + j]);
            r0 += s; r1 = fmaf(s, s, r1);
            r2 = fmaf(sG[t + 0], s, r2); r3 = fmaf(sG[D + t + 0], s, r3);
        }
        {
            const float s = silu_f(a.y + g_AnT[(t + 1) * PAD_N + j]);
            r0 += s; r1 = fmaf(s, s, r1);
            r2 = fmaf(sG[t + 1], s, r2); r3 = fmaf(sG[D + t + 1], s, r3);
        }
        {
            const float s = silu_f(a.z + g_AnT[(t + 2) * PAD_N + j]);
            r0 += s; r1 = fmaf(s, s, r1);
            r2 = fmaf(sG[t + 2], s, r2); r3 = fmaf(sG[D + t + 2], s, r3);
        }
        {
            const float s = silu_f(a.w + g_AnT[(t + 3) * PAD_N + j]);
            r0 += s; r1 = fmaf(s, s, r1);
            r2 = fmaf(sG[t + 3], s, r2); r3 = fmaf(sG[D + t + 3], s, r3);
        }
    }

    const float mu  = r0 * (1.0f / D);
    const float var = r1 * (1.0f / D) - mu * mu;
    const float rs  = rsqrtf(var + 1e-5f);
    const float o0  = rs * (r2 - mu * sC[0]) + sC[2];
    const float o1  = rs * (r3 - mu * sC[1]) + sC[3];
    g_table[pair] = make_float2(o0, o1);
}

// ---------------------------------------------------------------------------
// Kernel 3: gather. One int4 (2 batch elements) per thread.
// ---------------------------------------------------------------------------
__global__ void gather_kernel(const int4* __restrict__ x4,
                              float4* __restrict__ out4, int n4)
{
    const int t = blockIdx.x * blockDim.x + threadIdx.x;
    if (t >= n4) return;
    const int4 v = x4[t];
    const float2 a = g_table[(v.x - 1) * NMAX + (v.y - 1)];
    const float2 b = g_table[(v.z - 1) * NMAX + (v.w - 1)];
    out4[t] = make_float4(a.x, a.y, b.x, b.y);
}

__global__ void gather_tail_kernel(const int2* __restrict__ x2,
                                   float2* __restrict__ out2, int start, int n)
{
    const int t = start + blockIdx.x * blockDim.x + threadIdx.x;
    if (t >= n) return;
    const int2 v = x2[t];
    out2[t] = g_table[(v.x - 1) * NMAX + (v.y - 1)];
}

// ---------------------------------------------------------------------------
extern "C" void kernel_launch(void* const* d_in, const int* in_sizes, int n_in,
                              void* d_out, int out_size)
{
    const int*   x    = (const int*)  d_in[0];
    const float* emb  = (const float*)d_in[1];
    const float* Wp   = (const float*)d_in[2];
    const float* bp   = (const float*)d_in[3];
    const float* Wn   = (const float*)d_in[4];
    const float* bn   = (const float*)d_in[5];
    const float* W1   = (const float*)d_in[6];
    const float* b1   = (const float*)d_in[7];
    const float* ln_g = (const float*)d_in[8];
    const float* ln_b = (const float*)d_in[9];
    const float* W2   = (const float*)d_in[10];
    const float* b2   = (const float*)d_in[11];
    const float* Wr   = (const float*)d_in[12];
    const float* br   = (const float*)d_in[13];

    const int B = in_sizes[0] / 2;   // x is [B, 2]

    chains_kernel<<<1, 512>>>(emb, Wp, bp, Wn, bn, W1, b1,
                              ln_g, ln_b, W2, b2, Wr, br);

    {
        const int pairs  = PMAX * NMAX;          // 27848
        const int blocks = (pairs + 255) / 256;
        table_kernel<<<blocks, 256>>>();
    }

    {
        const int n4 = B / 2;                    // int4 count (2 elems each)
        if (n4 > 0) {
            const int blocks = (n4 + 255) / 256;
            gather_kernel<<<blocks, 256>>>((const int4*)x, (float4*)d_out, n4);
        }
        const int done = 2 * n4;
        if (done < B) {
            const int rem = B - done;
            gather_tail_kernel<<<(rem + 255) / 256, 256>>>(
                (const int2*)x, (float2*)d_out, done, B);
        }
    }
}